// round 8
// baseline (speedup 1.0000x reference)
#include <cuda_runtime.h>
#include <cuda_fp16.h>

// Grid4D quadrilinear sample:
//  1) transpose grid [R,X,Y,U,V] fp32 -> gridT [X,Y,U,V,R] fp16 (16B/cell)
//  2) bin points by [morton(u_hi,v_hi)][x][y][morton(u_mid,v_mid)] -> 65536 bins
//  3) persistent gather in bin order: warp-level line sharing + L2-resident frontier

#define RR 8
#define XX 9
#define YY 9
#define UU 512
#define VV 512
#define NS (XX * YY * UU * VV)     // 21,233,664 spatial cells
#define STR_R (NS)

#define NBINS 65536
#define NCAP (1 << 20)
#define GATHER_BLOCKS 740          // 5 per SM
#define CHUNK 256

__device__ uint4 g_gridT[(size_t)NS];            // ~340 MB fp16 transposed grid
__device__ unsigned int g_binCnt[NBINS];
__device__ unsigned int g_binCursor[NBINS];
__device__ float4 g_pts[NCAP];                   // sorted coords (16 MB)
__device__ unsigned int g_oidx[NCAP];            // original index (4 MB)
__device__ unsigned int g_ticket;

__device__ __forceinline__ unsigned int h2_to_u32(__half2 v) {
    return *reinterpret_cast<unsigned int*>(&v);
}
__device__ __forceinline__ __half2 u32_to_h2(unsigned int v) {
    return *reinterpret_cast<__half2*>(&v);
}

// ---------------- phase 1: transpose ----------------
__global__ void __launch_bounds__(256)
transpose_kernel(const float* __restrict__ grid) {
    int s = blockIdx.x * blockDim.x + threadIdx.x;
    if (s >= NS) return;
    uint4 packed;
    unsigned int* pu = &packed.x;
#pragma unroll
    for (int p = 0; p < 4; p++) {
        float a = __ldg(grid + (2 * p + 0) * STR_R + s);
        float b = __ldg(grid + (2 * p + 1) * STR_R + s);
        pu[p] = h2_to_u32(__floats2half2_rn(a, b));
    }
    g_gridT[s] = packed;
}

// ---------------- shared coordinate math ----------------
__device__ __forceinline__ void prep_dim(float c, float mn, float mx, int S,
                                         int& c0, int& dd, float& w0, float& w1) {
    float ind = (c - mn) / (mx - mn) * 2.0f - 1.0f;
    float pos = (ind + 1.0f) * 0.5f * (float)(S - 1);
    float fl = floorf(pos);
    int i0 = (int)fl;
    float f = pos - fl;
    w0 = 1.0f - f;
    w1 = f;
    if (i0 < 0 || i0 >= S) w0 = 0.0f;        // zero-padding semantics
    int i1 = i0 + 1;
    if (i1 < 0 || i1 >= S) w1 = 0.0f;
    int cc0 = min(max(i0, 0), S - 1);
    int cc1 = min(max(i1, 0), S - 1);
    c0 = cc0;
    dd = cc1 - cc0;                           // 0 or 1
}

__device__ __forceinline__ int base_idx(float c, float mn, float mx, int S) {
    float ind = (c - mn) / (mx - mn) * 2.0f - 1.0f;
    float pos = (ind + 1.0f) * 0.5f * (float)(S - 1);
    int i0 = (int)floorf(pos);
    return min(max(i0, 0), S - 1);
}

__device__ __forceinline__ int morton3(int a, int b) {  // a,b in [0,8) -> 6 bits
    return ((a & 1) << 0) | ((b & 1) << 1) |
           (((a >> 1) & 1) << 2) | (((b >> 1) & 1) << 3) |
           (((a >> 2) & 1) << 4) | (((b >> 2) & 1) << 5);
}

__device__ __forceinline__ int compute_bin(float4 c, const float* mn4, const float* mx4) {
    int x0 = min(base_idx(c.x, mn4[0], mx4[0], XX), 7);
    int y0 = min(base_idx(c.y, mn4[1], mx4[1], YY), 7);
    int u0 = base_idx(c.z, mn4[2], mx4[2], UU);
    int v0 = base_idx(c.w, mn4[3], mx4[3], VV);
    int hi  = morton3(u0 >> 6, v0 >> 6);                 // 6 bits
    int um = (u0 >> 4) & 3, vm = (v0 >> 4) & 3;
    int mid = (um & 1) | ((vm & 1) << 1) | ((um >> 1) << 2) | ((vm >> 1) << 3);  // 4 bits
    return (((((hi << 3) | x0) << 3) | y0) << 4) | mid;  // 16 bits
}

// ---------------- phase 2: binning ----------------
__global__ void __launch_bounds__(1024)
zero_kernel() {
    int b = blockIdx.x * blockDim.x + threadIdx.x;
    if (b < NBINS) g_binCnt[b] = 0;
    if (b == 0) g_ticket = 0;
}

__global__ void __launch_bounds__(256)
hist_kernel(const float4* __restrict__ xyuv,
            const float* __restrict__ mn4, const float* __restrict__ mx4, int n) {
    int i = blockIdx.x * blockDim.x + threadIdx.x;
    if (i < n) atomicAdd(&g_binCnt[compute_bin(xyuv[i], mn4, mx4)], 1u);
}

__global__ void __launch_bounds__(1024)
scan_kernel() {   // 1 block, 1024 threads, 64 consecutive bins each
    __shared__ unsigned int part[1024];
    int t = threadIdx.x;
    int base = t * 64;
    unsigned int vals[64];
    unsigned int sum = 0;
#pragma unroll
    for (int j = 0; j < 64; j++) {
        vals[j] = g_binCnt[base + j];
        sum += vals[j];
    }
    part[t] = sum;
    __syncthreads();
    for (int off = 1; off < 1024; off <<= 1) {
        unsigned int x = (t >= off) ? part[t - off] : 0u;
        __syncthreads();
        part[t] += x;
        __syncthreads();
    }
    unsigned int run = (t == 0) ? 0u : part[t - 1];
#pragma unroll
    for (int j = 0; j < 64; j++) {
        g_binCursor[base + j] = run;
        run += vals[j];
    }
}

__global__ void __launch_bounds__(256)
scatter_kernel(const float4* __restrict__ xyuv,
               const float* __restrict__ mn4, const float* __restrict__ mx4, int n) {
    int i = blockIdx.x * blockDim.x + threadIdx.x;
    if (i >= n) return;
    float4 c = xyuv[i];
    int bin = compute_bin(c, mn4, mx4);
    unsigned int pos = atomicAdd(&g_binCursor[bin], 1u);
    g_pts[pos] = c;
    g_oidx[pos] = (unsigned int)i;
}

// ---------------- phase 3: persistent gather with ticket queue ----------------
__global__ void __launch_bounds__(256)
gather_kernel(const float* __restrict__ mn4,
              const float* __restrict__ mx4,
              float* __restrict__ out, int n) {
    __shared__ unsigned int s_chunk;
    int nChunks = (n + CHUNK - 1) / CHUNK;

    for (;;) {
        __syncthreads();
        if (threadIdx.x == 0) s_chunk = atomicAdd(&g_ticket, 1u);
        __syncthreads();
        unsigned int chunk = s_chunk;
        if (chunk >= (unsigned int)nChunks) return;

        int t = (int)chunk * CHUNK + threadIdx.x;
        if (t < n) {
            float4 c = g_pts[t];

            int x0, y0, u0, v0, dx, dy, du, dv;
            float wx0, wx1, wy0, wy1, wu0, wu1, wv0, wv1;
            prep_dim(c.x, mn4[0], mx4[0], XX, x0, dx, wx0, wx1);
            prep_dim(c.y, mn4[1], mx4[1], YY, y0, dy, wy0, wy1);
            prep_dim(c.z, mn4[2], mx4[2], UU, u0, du, wu0, wu1);
            prep_dim(c.w, mn4[3], mx4[3], VV, v0, dv, wv0, wv1);

            int sidx[8];
            float w[8];
#pragma unroll
            for (int k = 0; k < 8; k++) {
                int xa = (k >> 2) & 1;
                int ya = (k >> 1) & 1;
                int ua = k & 1;
                int xi = x0 + (xa ? dx : 0);
                int yi = y0 + (ya ? dy : 0);
                int ui = u0 + (ua ? du : 0);
                sidx[k] = ((xi * YY + yi) * UU + ui) * VV + v0;
                w[k] = (xa ? wx1 : wx0) * (ya ? wy1 : wy0) * (ua ? wu1 : wu0);
            }

            float acc[RR];
#pragma unroll
            for (int r = 0; r < RR; r++) acc[r] = 0.0f;

#pragma unroll 2
            for (int k = 0; k < 8; k++) {
                int s0 = sidx[k];
                uint4 A = g_gridT[s0];
                uint4 B = g_gridT[s0 + dv];
                float wa = w[k] * wv0;
                float wb = w[k] * wv1;
                const unsigned int* au = &A.x;
                const unsigned int* bu = &B.x;
#pragma unroll
                for (int p = 0; p < 4; p++) {
                    float2 fa = __half22float2(u32_to_h2(au[p]));
                    float2 fb = __half22float2(u32_to_h2(bu[p]));
                    acc[2 * p + 0] = fmaf(wa, fa.x, fmaf(wb, fb.x, acc[2 * p + 0]));
                    acc[2 * p + 1] = fmaf(wa, fa.y, fmaf(wb, fb.y, acc[2 * p + 1]));
                }
            }

            unsigned int oi = g_oidx[t];
            float4* o4 = reinterpret_cast<float4*>(out + (size_t)oi * RR);
            o4[0] = make_float4(acc[0], acc[1], acc[2], acc[3]);
            o4[1] = make_float4(acc[4], acc[5], acc[6], acc[7]);
        }
    }
}

extern "C" void kernel_launch(void* const* d_in, const int* in_sizes, int n_in,
                              void* d_out, int out_size) {
    const float4* xyuv = (const float4*)d_in[0];
    const float* grid  = (const float*)d_in[1];
    const float* mn4   = (const float*)d_in[2];
    const float* mx4   = (const float*)d_in[3];
    float* out = (float*)d_out;

    int n = in_sizes[0] / 4;  // 1,048,576 points
    if (n > NCAP) n = NCAP;

    int tThreads = 256;
    int tBlocks = (NS + tThreads - 1) / tThreads;
    transpose_kernel<<<tBlocks, tThreads>>>(grid);

    int pBlocks = (n + 255) / 256;
    zero_kernel<<<NBINS / 1024, 1024>>>();
    hist_kernel<<<pBlocks, 256>>>(xyuv, mn4, mx4, n);
    scan_kernel<<<1, 1024>>>();
    scatter_kernel<<<pBlocks, 256>>>(xyuv, mn4, mx4, n);

    gather_kernel<<<GATHER_BLOCKS, 256>>>(mn4, mx4, out, n);
}

// round 9
// speedup vs baseline: 1.2407x; 1.2407x over previous
#include <cuda_runtime.h>
#include <cuda_fp16.h>

// Grid4D quadrilinear sample:
//  1) transpose grid [R,X,Y,U,V] fp32 -> gridT [X,Y,U,V,R] fp16 (16B/cell)
//  2) bin points by [morton(u_hi,v_hi)][x][y][morton(u_mid,v_mid)] -> 65536 bins
//     (hierarchical 3-stage scan, 64 blocks)
//  3) persistent gather in bin order: warp-level line sharing + L2-resident frontier

#define RR 8
#define XX 9
#define YY 9
#define UU 512
#define VV 512
#define NS (XX * YY * UU * VV)     // 21,233,664 spatial cells
#define STR_R (NS)

#define NBINS 65536
#define SCAN_BLOCKS 64
#define NCAP (1 << 20)
#define GATHER_BLOCKS 740          // 5 per SM
#define CHUNK 256

__device__ uint4 g_gridT[(size_t)NS];            // ~340 MB fp16 transposed grid
__device__ unsigned int g_binCnt[NBINS];
__device__ unsigned int g_binCursor[NBINS];
__device__ unsigned int g_blkSum[SCAN_BLOCKS];
__device__ unsigned int g_blkOff[SCAN_BLOCKS];
__device__ float4 g_pts[NCAP];                   // sorted coords (16 MB)
__device__ unsigned int g_oidx[NCAP];            // original index (4 MB)
__device__ unsigned int g_ticket;

__device__ __forceinline__ unsigned int h2_to_u32(__half2 v) {
    return *reinterpret_cast<unsigned int*>(&v);
}
__device__ __forceinline__ __half2 u32_to_h2(unsigned int v) {
    return *reinterpret_cast<__half2*>(&v);
}

// ---------------- phase 1: transpose ----------------
__global__ void __launch_bounds__(256)
transpose_kernel(const float* __restrict__ grid) {
    int s = blockIdx.x * blockDim.x + threadIdx.x;
    if (s >= NS) return;
    uint4 packed;
    unsigned int* pu = &packed.x;
#pragma unroll
    for (int p = 0; p < 4; p++) {
        float a = __ldg(grid + (2 * p + 0) * STR_R + s);
        float b = __ldg(grid + (2 * p + 1) * STR_R + s);
        pu[p] = h2_to_u32(__floats2half2_rn(a, b));
    }
    g_gridT[s] = packed;
}

// ---------------- shared coordinate math ----------------
__device__ __forceinline__ void prep_dim(float c, float mn, float mx, int S,
                                         int& c0, int& dd, float& w0, float& w1) {
    float ind = (c - mn) / (mx - mn) * 2.0f - 1.0f;
    float pos = (ind + 1.0f) * 0.5f * (float)(S - 1);
    float fl = floorf(pos);
    int i0 = (int)fl;
    float f = pos - fl;
    w0 = 1.0f - f;
    w1 = f;
    if (i0 < 0 || i0 >= S) w0 = 0.0f;        // zero-padding semantics
    int i1 = i0 + 1;
    if (i1 < 0 || i1 >= S) w1 = 0.0f;
    int cc0 = min(max(i0, 0), S - 1);
    int cc1 = min(max(i1, 0), S - 1);
    c0 = cc0;
    dd = cc1 - cc0;                           // 0 or 1
}

__device__ __forceinline__ int base_idx(float c, float mn, float mx, int S) {
    float ind = (c - mn) / (mx - mn) * 2.0f - 1.0f;
    float pos = (ind + 1.0f) * 0.5f * (float)(S - 1);
    int i0 = (int)floorf(pos);
    return min(max(i0, 0), S - 1);
}

__device__ __forceinline__ int morton3(int a, int b) {  // a,b in [0,8) -> 6 bits
    return ((a & 1) << 0) | ((b & 1) << 1) |
           (((a >> 1) & 1) << 2) | (((b >> 1) & 1) << 3) |
           (((a >> 2) & 1) << 4) | (((b >> 2) & 1) << 5);
}

__device__ __forceinline__ int compute_bin(float4 c, const float* mn4, const float* mx4) {
    int x0 = min(base_idx(c.x, mn4[0], mx4[0], XX), 7);
    int y0 = min(base_idx(c.y, mn4[1], mx4[1], YY), 7);
    int u0 = base_idx(c.z, mn4[2], mx4[2], UU);
    int v0 = base_idx(c.w, mn4[3], mx4[3], VV);
    int hi  = morton3(u0 >> 6, v0 >> 6);                 // 6 bits
    int um = (u0 >> 4) & 3, vm = (v0 >> 4) & 3;
    int mid = (um & 1) | ((vm & 1) << 1) | ((um >> 1) << 2) | ((vm >> 1) << 3);  // 4 bits
    return (((((hi << 3) | x0) << 3) | y0) << 4) | mid;  // 16 bits
}

// ---------------- phase 2: binning ----------------
__global__ void __launch_bounds__(1024)
zero_kernel() {
    int b = blockIdx.x * blockDim.x + threadIdx.x;
    if (b < NBINS) g_binCnt[b] = 0;
    if (b == 0) g_ticket = 0;
}

__global__ void __launch_bounds__(256)
hist_kernel(const float4* __restrict__ xyuv,
            const float* __restrict__ mn4, const float* __restrict__ mx4, int n) {
    int i = blockIdx.x * blockDim.x + threadIdx.x;
    if (i < n) atomicAdd(&g_binCnt[compute_bin(xyuv[i], mn4, mx4)], 1u);
}

// stage 1: per-block exclusive scan of 1024 bins, emit block total
__global__ void __launch_bounds__(1024)
scan_local_kernel() {
    __shared__ unsigned int s[1024];
    int t = threadIdx.x;
    int b = blockIdx.x * 1024 + t;
    unsigned int v = g_binCnt[b];
    s[t] = v;
    __syncthreads();
    for (int off = 1; off < 1024; off <<= 1) {
        unsigned int x = (t >= off) ? s[t - off] : 0u;
        __syncthreads();
        s[t] += x;
        __syncthreads();
    }
    g_binCursor[b] = s[t] - v;   // exclusive
    if (t == 1023) g_blkSum[blockIdx.x] = s[t];
}

// stage 2: scan the 64 block totals
__global__ void __launch_bounds__(64)
scan_top_kernel() {
    __shared__ unsigned int s[SCAN_BLOCKS];
    int t = threadIdx.x;
    unsigned int v = g_blkSum[t];
    s[t] = v;
    __syncthreads();
    for (int off = 1; off < SCAN_BLOCKS; off <<= 1) {
        unsigned int x = (t >= off) ? s[t - off] : 0u;
        __syncthreads();
        s[t] += x;
        __syncthreads();
    }
    g_blkOff[t] = s[t] - v;      // exclusive
}

// stage 3: add block offsets
__global__ void __launch_bounds__(1024)
scan_add_kernel() {
    int b = blockIdx.x * 1024 + threadIdx.x;
    g_binCursor[b] += g_blkOff[blockIdx.x];
}

__global__ void __launch_bounds__(256)
scatter_kernel(const float4* __restrict__ xyuv,
               const float* __restrict__ mn4, const float* __restrict__ mx4, int n) {
    int i = blockIdx.x * blockDim.x + threadIdx.x;
    if (i >= n) return;
    float4 c = xyuv[i];
    int bin = compute_bin(c, mn4, mx4);
    unsigned int pos = atomicAdd(&g_binCursor[bin], 1u);
    g_pts[pos] = c;
    g_oidx[pos] = (unsigned int)i;
}

// ---------------- phase 3: persistent gather with ticket queue ----------------
__global__ void __launch_bounds__(256)
gather_kernel(const float* __restrict__ mn4,
              const float* __restrict__ mx4,
              float* __restrict__ out, int n) {
    __shared__ unsigned int s_chunk;
    int nChunks = (n + CHUNK - 1) / CHUNK;

    for (;;) {
        __syncthreads();
        if (threadIdx.x == 0) s_chunk = atomicAdd(&g_ticket, 1u);
        __syncthreads();
        unsigned int chunk = s_chunk;
        if (chunk >= (unsigned int)nChunks) return;

        int t = (int)chunk * CHUNK + threadIdx.x;
        if (t < n) {
            float4 c = g_pts[t];

            int x0, y0, u0, v0, dx, dy, du, dv;
            float wx0, wx1, wy0, wy1, wu0, wu1, wv0, wv1;
            prep_dim(c.x, mn4[0], mx4[0], XX, x0, dx, wx0, wx1);
            prep_dim(c.y, mn4[1], mx4[1], YY, y0, dy, wy0, wy1);
            prep_dim(c.z, mn4[2], mx4[2], UU, u0, du, wu0, wu1);
            prep_dim(c.w, mn4[3], mx4[3], VV, v0, dv, wv0, wv1);

            int sidx[8];
            float w[8];
#pragma unroll
            for (int k = 0; k < 8; k++) {
                int xa = (k >> 2) & 1;
                int ya = (k >> 1) & 1;
                int ua = k & 1;
                int xi = x0 + (xa ? dx : 0);
                int yi = y0 + (ya ? dy : 0);
                int ui = u0 + (ua ? du : 0);
                sidx[k] = ((xi * YY + yi) * UU + ui) * VV + v0;
                w[k] = (xa ? wx1 : wx0) * (ya ? wy1 : wy0) * (ua ? wu1 : wu0);
            }

            float acc[RR];
#pragma unroll
            for (int r = 0; r < RR; r++) acc[r] = 0.0f;

#pragma unroll 2
            for (int k = 0; k < 8; k++) {
                int s0 = sidx[k];
                uint4 A = g_gridT[s0];
                uint4 B = g_gridT[s0 + dv];
                float wa = w[k] * wv0;
                float wb = w[k] * wv1;
                const unsigned int* au = &A.x;
                const unsigned int* bu = &B.x;
#pragma unroll
                for (int p = 0; p < 4; p++) {
                    float2 fa = __half22float2(u32_to_h2(au[p]));
                    float2 fb = __half22float2(u32_to_h2(bu[p]));
                    acc[2 * p + 0] = fmaf(wa, fa.x, fmaf(wb, fb.x, acc[2 * p + 0]));
                    acc[2 * p + 1] = fmaf(wa, fa.y, fmaf(wb, fb.y, acc[2 * p + 1]));
                }
            }

            unsigned int oi = g_oidx[t];
            float4* o4 = reinterpret_cast<float4*>(out + (size_t)oi * RR);
            o4[0] = make_float4(acc[0], acc[1], acc[2], acc[3]);
            o4[1] = make_float4(acc[4], acc[5], acc[6], acc[7]);
        }
    }
}

extern "C" void kernel_launch(void* const* d_in, const int* in_sizes, int n_in,
                              void* d_out, int out_size) {
    const float4* xyuv = (const float4*)d_in[0];
    const float* grid  = (const float*)d_in[1];
    const float* mn4   = (const float*)d_in[2];
    const float* mx4   = (const float*)d_in[3];
    float* out = (float*)d_out;

    int n = in_sizes[0] / 4;  // 1,048,576 points
    if (n > NCAP) n = NCAP;

    int tThreads = 256;
    int tBlocks = (NS + tThreads - 1) / tThreads;
    transpose_kernel<<<tBlocks, tThreads>>>(grid);

    int pBlocks = (n + 255) / 256;
    zero_kernel<<<NBINS / 1024, 1024>>>();
    hist_kernel<<<pBlocks, 256>>>(xyuv, mn4, mx4, n);
    scan_local_kernel<<<SCAN_BLOCKS, 1024>>>();
    scan_top_kernel<<<1, SCAN_BLOCKS>>>();
    scan_add_kernel<<<SCAN_BLOCKS, 1024>>>();
    scatter_kernel<<<pBlocks, 256>>>(xyuv, mn4, mx4, n);

    gather_kernel<<<GATHER_BLOCKS, 256>>>(mn4, mx4, out, n);
}